// round 2
// baseline (speedup 1.0000x reference)
#include <cuda_runtime.h>
#include <math.h>
#include <math_constants.h>

#define SEQ  4096
#define DIM  1024
#define NH   16
#define HD   64
#define HID  4096

// ---------------- scratch (device globals; no allocations allowed) ----------
__device__ float g_xn[SEQ * DIM];
__device__ float g_qb[SEQ * DIM];
__device__ float g_kb[SEQ * DIM];
__device__ float g_vb[SEQ * DIM];
__device__ float g_ao[SEQ * DIM];
__device__ float g_hb[SEQ * DIM];
__device__ float g_hn[SEQ * DIM];
__device__ float g_ff[SEQ * HID];
__device__ float g_cos[SEQ * (HD / 2)];
__device__ float g_sin[SEQ * (HD / 2)];

// ---------------- RoPE tables (matches reference fp32 math) -----------------
__global__ void rope_tab_k(float* __restrict__ ct, float* __restrict__ st) {
    int idx = blockIdx.x * blockDim.x + threadIdx.x;   // SEQ*32 total
    int t = idx >> 5;
    int i = idx & 31;
    float inv = powf(10000.0f, -(float)i * (1.0f / 32.0f));
    float ang = (float)t * inv;
    ct[idx] = cosf(ang);
    st[idx] = sinf(ang);
}

// ---------------- RMSNorm: one block per row of 1024 -------------------------
__global__ __launch_bounds__(256) void rmsnorm_k(
    const float* __restrict__ x, const float* __restrict__ g, float* __restrict__ o)
{
    int row = blockIdx.x;
    int tid = threadIdx.x;
    const float4 v = ((const float4*)(x + (size_t)row * DIM))[tid];
    float s = v.x * v.x + v.y * v.y + v.z * v.z + v.w * v.w;
    #pragma unroll
    for (int m = 16; m > 0; m >>= 1) s += __shfl_xor_sync(0xffffffffu, s, m);
    __shared__ float red[8];
    if ((tid & 31) == 0) red[tid >> 5] = s;
    __syncthreads();
    float tot = red[0] + red[1] + red[2] + red[3] + red[4] + red[5] + red[6] + red[7];
    float r = rsqrtf(tot * (1.0f / DIM) + 1e-6f);
    const float4 gv = ((const float4*)g)[tid];
    float4 ov = make_float4(v.x * r * gv.x, v.y * r * gv.y, v.z * r * gv.z, v.w * r * gv.w);
    ((float4*)(o + (size_t)row * DIM))[tid] = ov;
}

// ---------------- Generic SGEMM: C[M,N] = A[M,K] * B[N,K]^T ------------------
// Both A and B are row-major with K contiguous (x @ W.T pattern).
// 2-stage smem double buffering: LDGs for tile t+1 issued before FFMAs of
// tile t; one __syncthreads per K-tile.
// EPI: 0=none, 1=RoPE, 2=residual add (aux), 3=SiLU, 4=multiply by aux (gate)
template<int EPI>
__global__ __launch_bounds__(256) void gemm_k(
    const float* __restrict__ A, const float* __restrict__ B,
    float* __restrict__ C, const float* aux,
    const float* __restrict__ cosT, const float* __restrict__ sinT,
    int M, int N, int K)
{
    __shared__ float As[2][16][128];
    __shared__ float Bs[2][16][128];

    const int tid = threadIdx.x;
    const int tx  = tid & 15;       // 16 column groups of 8
    const int ty  = tid >> 4;       // 16 row groups of 8
    const int m0  = blockIdx.y * 128;
    const int n0  = blockIdx.x * 128;

    const int ar = tid >> 2;            // 0..63
    const int ac = (tid & 3) << 2;      // 0,4,8,12

    const float* Aptr = A + (size_t)(m0 + ar) * K + ac;
    const float* Bptr = B + (size_t)(n0 + ar) * K + ac;

    float acc[8][8];
    #pragma unroll
    for (int i = 0; i < 8; ++i)
        #pragma unroll
        for (int j = 0; j < 8; ++j) acc[i][j] = 0.0f;

    // prologue: load tile 0 into buffer 0
    float4 a0 = *(const float4*)(Aptr);
    float4 a1 = *(const float4*)(Aptr + (size_t)64 * K);
    float4 b0 = *(const float4*)(Bptr);
    float4 b1 = *(const float4*)(Bptr + (size_t)64 * K);
    As[0][ac + 0][ar] = a0.x; As[0][ac + 1][ar] = a0.y; As[0][ac + 2][ar] = a0.z; As[0][ac + 3][ar] = a0.w;
    As[0][ac + 0][ar + 64] = a1.x; As[0][ac + 1][ar + 64] = a1.y; As[0][ac + 2][ar + 64] = a1.z; As[0][ac + 3][ar + 64] = a1.w;
    Bs[0][ac + 0][ar] = b0.x; Bs[0][ac + 1][ar] = b0.y; Bs[0][ac + 2][ar] = b0.z; Bs[0][ac + 3][ar] = b0.w;
    Bs[0][ac + 0][ar + 64] = b1.x; Bs[0][ac + 1][ar + 64] = b1.y; Bs[0][ac + 2][ar + 64] = b1.z; Bs[0][ac + 3][ar + 64] = b1.w;
    __syncthreads();

    int buf = 0;
    for (int k0 = 16; k0 <= K; k0 += 16) {
        // prefetch next tile into registers (hides LDG latency behind FFMAs)
        if (k0 < K) {
            a0 = *(const float4*)(Aptr + k0);
            a1 = *(const float4*)(Aptr + (size_t)64 * K + k0);
            b0 = *(const float4*)(Bptr + k0);
            b1 = *(const float4*)(Bptr + (size_t)64 * K + k0);
        }

        // compute on current buffer
        #pragma unroll
        for (int kk = 0; kk < 16; ++kk) {
            float a[8], b[8];
            *(float4*)(a)     = *(const float4*)(&As[buf][kk][ty * 8]);
            *(float4*)(a + 4) = *(const float4*)(&As[buf][kk][ty * 8 + 4]);
            *(float4*)(b)     = *(const float4*)(&Bs[buf][kk][tx * 8]);
            *(float4*)(b + 4) = *(const float4*)(&Bs[buf][kk][tx * 8 + 4]);
            #pragma unroll
            for (int i = 0; i < 8; ++i)
                #pragma unroll
                for (int j = 0; j < 8; ++j)
                    acc[i][j] += a[i] * b[j];
        }

        // stage next tile into the other buffer
        if (k0 < K) {
            int nb = buf ^ 1;
            As[nb][ac + 0][ar] = a0.x; As[nb][ac + 1][ar] = a0.y; As[nb][ac + 2][ar] = a0.z; As[nb][ac + 3][ar] = a0.w;
            As[nb][ac + 0][ar + 64] = a1.x; As[nb][ac + 1][ar + 64] = a1.y; As[nb][ac + 2][ar + 64] = a1.z; As[nb][ac + 3][ar + 64] = a1.w;
            Bs[nb][ac + 0][ar] = b0.x; Bs[nb][ac + 1][ar] = b0.y; Bs[nb][ac + 2][ar] = b0.z; Bs[nb][ac + 3][ar] = b0.w;
            Bs[nb][ac + 0][ar + 64] = b1.x; Bs[nb][ac + 1][ar + 64] = b1.y; Bs[nb][ac + 2][ar + 64] = b1.z; Bs[nb][ac + 3][ar + 64] = b1.w;
            __syncthreads();
            buf = nb;
        }
    }

    #pragma unroll
    for (int i = 0; i < 8; ++i) {
        const int m = m0 + ty * 8 + i;
        const int n = n0 + tx * 8;
        float o[8];
        #pragma unroll
        for (int j = 0; j < 8; ++j) o[j] = acc[i][j];

        if (EPI == 1) {
            #pragma unroll
            for (int p = 0; p < 4; ++p) {
                int nn = n + 2 * p;
                int pi = (nn & 63) >> 1;
                float c = cosT[m * 32 + pi];
                float s = sinT[m * 32 + pi];
                float re = o[2 * p], im = o[2 * p + 1];
                o[2 * p]     = re * c - im * s;
                o[2 * p + 1] = re * s + im * c;
            }
        } else if (EPI == 2) {
            #pragma unroll
            for (int j = 0; j < 8; ++j) o[j] += aux[(size_t)m * N + n + j];
        } else if (EPI == 3) {
            #pragma unroll
            for (int j = 0; j < 8; ++j) {
                float v = o[j];
                o[j] = v / (1.0f + __expf(-v));
            }
        } else if (EPI == 4) {
            #pragma unroll
            for (int j = 0; j < 8; ++j) o[j] = aux[(size_t)m * N + n + j] * o[j];
        }

        *(float4*)(C + (size_t)m * N + n)     = make_float4(o[0], o[1], o[2], o[3]);
        *(float4*)(C + (size_t)m * N + n + 4) = make_float4(o[4], o[5], o[6], o[7]);
    }
}

// ---------------- Flash attention: Br=64 queries, Bc=32 keys per tile --------
// grid = (SEQ/64, NH). 16 heads, hd=64, full (non-causal) softmax.
__global__ __launch_bounds__(256) void attn_k(
    const float* __restrict__ Q, const float* __restrict__ Kg,
    const float* __restrict__ Vg, float* __restrict__ O)
{
    __shared__ float Qs[64][68];    // [d][r]  (transposed)
    __shared__ float Ks[64][36];    // [d][c]  (transposed)
    __shared__ float Vs[32][68];    // [c][d]
    __shared__ float Ps[64][36];    // [r][c]
    __shared__ float alpha_s[64];
    __shared__ float l_s[64];

    const int tid  = threadIdx.x;
    const int h    = blockIdx.y;
    const int q0   = blockIdx.x * 64;
    const int hoff = h * HD;

    // Load Q tile transposed: thread r = tid/4, 16 d's each
    {
        int r  = tid >> 2;
        int ds = (tid & 3) << 4;
        const float* qp = Q + (size_t)(q0 + r) * DIM + hoff + ds;
        #pragma unroll
        for (int v4 = 0; v4 < 4; ++v4) {
            float4 q4 = *(const float4*)(qp + v4 * 4);
            Qs[ds + v4 * 4 + 0][r] = q4.x;
            Qs[ds + v4 * 4 + 1][r] = q4.y;
            Qs[ds + v4 * 4 + 2][r] = q4.z;
            Qs[ds + v4 * 4 + 3][r] = q4.w;
        }
    }

    const int ty  = tid >> 3;   // 0..31 -> S rows ty*2
    const int txs = tid & 7;    // S cols txs*4
    const int tyo = tid >> 4;   // 0..15 -> O rows tyo*4
    const int txo = tid & 15;   // O cols txo*4
    const int r0 = ty * 2, c0s = txs * 4, rO = tyo * 4, cO = txo * 4;

    float mi[2] = {-CUDART_INF_F, -CUDART_INF_F};
    float li[2] = {0.0f, 0.0f};
    float oacc[4][4];
    #pragma unroll
    for (int i = 0; i < 4; ++i)
        #pragma unroll
        for (int j = 0; j < 4; ++j) oacc[i][j] = 0.0f;

    for (int t0 = 0; t0 < SEQ; t0 += 32) {
        __syncthreads();   // previous iteration's consumers done
        // Load K tile transposed + V tile direct
        {
            int c  = tid >> 3;          // 0..31
            int ds = (tid & 7) << 3;    // 0,8,...,56
            const float* kp = Kg + (size_t)(t0 + c) * DIM + hoff + ds;
            float4 k0v = *(const float4*)(kp);
            float4 k1v = *(const float4*)(kp + 4);
            Ks[ds + 0][c] = k0v.x; Ks[ds + 1][c] = k0v.y; Ks[ds + 2][c] = k0v.z; Ks[ds + 3][c] = k0v.w;
            Ks[ds + 4][c] = k1v.x; Ks[ds + 5][c] = k1v.y; Ks[ds + 6][c] = k1v.z; Ks[ds + 7][c] = k1v.w;
            const float* vp = Vg + (size_t)(t0 + c) * DIM + hoff + ds;
            *(float4*)&Vs[c][ds]     = *(const float4*)(vp);
            *(float4*)&Vs[c][ds + 4] = *(const float4*)(vp + 4);
        }
        __syncthreads();

        // S = (Q K^T) * 1/sqrt(64)
        float s[2][4];
        #pragma unroll
        for (int i = 0; i < 2; ++i)
            #pragma unroll
            for (int j = 0; j < 4; ++j) s[i][j] = 0.0f;

        #pragma unroll 8
        for (int kk = 0; kk < 64; ++kk) {
            float qa = Qs[kk][r0];
            float qb = Qs[kk][r0 + 1];
            float4 kb = *(const float4*)(&Ks[kk][c0s]);
            s[0][0] += qa * kb.x; s[0][1] += qa * kb.y; s[0][2] += qa * kb.z; s[0][3] += qa * kb.w;
            s[1][0] += qb * kb.x; s[1][1] += qb * kb.y; s[1][2] += qb * kb.z; s[1][3] += qb * kb.w;
        }

        #pragma unroll
        for (int i = 0; i < 2; ++i) {
            #pragma unroll
            for (int j = 0; j < 4; ++j) s[i][j] *= 0.125f;
            float mt = fmaxf(fmaxf(s[i][0], s[i][1]), fmaxf(s[i][2], s[i][3]));
            mt = fmaxf(mt, __shfl_xor_sync(0xffffffffu, mt, 1, 8));
            mt = fmaxf(mt, __shfl_xor_sync(0xffffffffu, mt, 2, 8));
            mt = fmaxf(mt, __shfl_xor_sync(0xffffffffu, mt, 4, 8));
            float mn = fmaxf(mi[i], mt);
            float al = __expf(mi[i] - mn);
            mi[i] = mn;
            float p[4], rs = 0.0f;
            #pragma unroll
            for (int j = 0; j < 4; ++j) { p[j] = __expf(s[i][j] - mn); rs += p[j]; }
            rs += __shfl_xor_sync(0xffffffffu, rs, 1, 8);
            rs += __shfl_xor_sync(0xffffffffu, rs, 2, 8);
            rs += __shfl_xor_sync(0xffffffffu, rs, 4, 8);
            li[i] = li[i] * al + rs;
            if (txs == 0) alpha_s[r0 + i] = al;
            *(float4*)(&Ps[r0 + i][c0s]) = make_float4(p[0], p[1], p[2], p[3]);
        }
        __syncthreads();

        // O = O*alpha + P @ V
        #pragma unroll
        for (int i = 0; i < 4; ++i) {
            float al = alpha_s[rO + i];
            #pragma unroll
            for (int j = 0; j < 4; ++j) oacc[i][j] *= al;
        }
        #pragma unroll 8
        for (int kk = 0; kk < 32; ++kk) {
            float4 vb = *(const float4*)(&Vs[kk][cO]);
            #pragma unroll
            for (int i = 0; i < 4; ++i) {
                float p = Ps[rO + i][kk];
                oacc[i][0] += p * vb.x;
                oacc[i][1] += p * vb.y;
                oacc[i][2] += p * vb.z;
                oacc[i][3] += p * vb.w;
            }
        }
    }

    // finalize: O /= l
    if (txs == 0) { l_s[r0] = li[0]; l_s[r0 + 1] = li[1]; }
    __syncthreads();
    #pragma unroll
    for (int i = 0; i < 4; ++i) {
        float inv = 1.0f / l_s[rO + i];
        float4 ov = make_float4(oacc[i][0] * inv, oacc[i][1] * inv,
                                oacc[i][2] * inv, oacc[i][3] * inv);
        *(float4*)(O + (size_t)(q0 + rO + i) * DIM + hoff + cO) = ov;
    }
}

// ---------------- launch ------------------------------------------------------
extern "C" void kernel_launch(void* const* d_in, const int* in_sizes, int n_in,
                              void* d_out, int out_size)
{
    (void)in_sizes; (void)n_in; (void)out_size;
    const float* x  = (const float*)d_in[0];
    const float* wq = (const float*)d_in[1];
    const float* wk = (const float*)d_in[2];
    const float* wv = (const float*)d_in[3];
    const float* wo = (const float*)d_in[4];
    const float* w1 = (const float*)d_in[5];
    const float* w2 = (const float*)d_in[6];
    const float* w3 = (const float*)d_in[7];
    const float* ga = (const float*)d_in[8];
    const float* gf = (const float*)d_in[9];
    float* out = (float*)d_out;

    float *xn, *qb, *kb, *vb, *ao, *hb, *hn, *ff, *ct, *st;
    cudaGetSymbolAddress((void**)&xn, g_xn);
    cudaGetSymbolAddress((void**)&qb, g_qb);
    cudaGetSymbolAddress((void**)&kb, g_kb);
    cudaGetSymbolAddress((void**)&vb, g_vb);
    cudaGetSymbolAddress((void**)&ao, g_ao);
    cudaGetSymbolAddress((void**)&hb, g_hb);
    cudaGetSymbolAddress((void**)&hn, g_hn);
    cudaGetSymbolAddress((void**)&ff, g_ff);
    cudaGetSymbolAddress((void**)&ct, g_cos);
    cudaGetSymbolAddress((void**)&st, g_sin);

    // RoPE tables
    rope_tab_k<<<(SEQ * 32) / 256, 256>>>(ct, st);

    // xn = rmsnorm(x, g_attn)
    rmsnorm_k<<<SEQ, 256>>>(x, ga, xn);

    dim3 blk(256);
    dim3 gD(DIM / 128, SEQ / 128);   // N=1024 outputs
    dim3 gH(HID / 128, SEQ / 128);   // N=4096 outputs

    // q/k (with fused RoPE), v
    gemm_k<1><<<gD, blk>>>(xn, wq, qb, nullptr, ct, st, SEQ, DIM, DIM);
    gemm_k<1><<<gD, blk>>>(xn, wk, kb, nullptr, ct, st, SEQ, DIM, DIM);
    gemm_k<0><<<gD, blk>>>(xn, wv, vb, nullptr, nullptr, nullptr, SEQ, DIM, DIM);

    // attention
    attn_k<<<dim3(SEQ / 64, NH), 256>>>(qb, kb, vb, ao);

    // h = x + attn @ wo^T
    gemm_k<2><<<gD, blk>>>(ao, wo, hb, x, nullptr, nullptr, SEQ, DIM, DIM);

    // hn = rmsnorm(h, g_ffn)
    rmsnorm_k<<<SEQ, 256>>>(hb, gf, hn);

    // ff = silu(hn @ w1^T);  ff *= hn @ w3^T
    gemm_k<3><<<gH, blk>>>(hn, w1, ff, nullptr, nullptr, nullptr, SEQ, HID, DIM);
    gemm_k<4><<<gH, blk>>>(hn, w3, ff, ff, nullptr, nullptr, SEQ, HID, DIM);

    // out = h + ff @ w2^T
    gemm_k<2><<<gD, blk>>>(ff, w2, out, hb, nullptr, nullptr, SEQ, DIM, HID);
}

// round 13
// speedup vs baseline: 2.8545x; 2.8545x over previous
#include <cuda_runtime.h>
#include <math.h>
#include <math_constants.h>
#include <stdint.h>

#define SEQ  4096
#define DIM  1024
#define NH   16
#define HD   64
#define HID  4096

// ---------------- scratch (device globals; no allocations allowed) ----------
__device__ float g_xn[SEQ * DIM];
__device__ float g_qb[SEQ * DIM];
__device__ float g_kb[SEQ * DIM];
__device__ float g_vb[SEQ * DIM];
__device__ float g_ao[SEQ * DIM];
__device__ float g_hb[SEQ * DIM];
__device__ float g_hn[SEQ * DIM];
__device__ float g_ff[SEQ * HID];
__device__ float g_cos[SEQ * (HD / 2)];
__device__ float g_sin[SEQ * (HD / 2)];

// ---------------- RoPE tables (matches reference fp32 math) -----------------
__global__ void rope_tab_k(float* __restrict__ ct, float* __restrict__ st) {
    int idx = blockIdx.x * blockDim.x + threadIdx.x;   // SEQ*32 total
    int t = idx >> 5;
    int i = idx & 31;
    float inv = powf(10000.0f, -(float)i * (1.0f / 32.0f));
    float ang = (float)t * inv;
    ct[idx] = cosf(ang);
    st[idx] = sinf(ang);
}

// ---------------- RMSNorm: one block per row of 1024 -------------------------
__global__ __launch_bounds__(256) void rmsnorm_k(
    const float* __restrict__ x, const float* __restrict__ g, float* __restrict__ o)
{
    int row = blockIdx.x;
    int tid = threadIdx.x;
    const float4 v = ((const float4*)(x + (size_t)row * DIM))[tid];
    float s = v.x * v.x + v.y * v.y + v.z * v.z + v.w * v.w;
    #pragma unroll
    for (int m = 16; m > 0; m >>= 1) s += __shfl_xor_sync(0xffffffffu, s, m);
    __shared__ float red[8];
    if ((tid & 31) == 0) red[tid >> 5] = s;
    __syncthreads();
    float tot = red[0] + red[1] + red[2] + red[3] + red[4] + red[5] + red[6] + red[7];
    float r = rsqrtf(tot * (1.0f / DIM) + 1e-6f);
    const float4 gv = ((const float4*)g)[tid];
    float4 ov = make_float4(v.x * r * gv.x, v.y * r * gv.y, v.z * r * gv.z, v.w * r * gv.w);
    ((float4*)(o + (size_t)row * DIM))[tid] = ov;
}

// ---------------- TF32 helpers ----------------------------------------------
__device__ __forceinline__ float to_tf32(float x) {
    float r;
    asm("cvt.rna.tf32.f32 %0, %1;" : "=f"(r) : "f"(x));
    return r;
}
__device__ __forceinline__ float4 cvt4(float4 v) {
    v.x = to_tf32(v.x); v.y = to_tf32(v.y); v.z = to_tf32(v.z); v.w = to_tf32(v.w);
    return v;
}
__device__ __forceinline__ void mma_tf32(float* d, const uint32_t* a, const uint32_t* b) {
    asm volatile(
        "mma.sync.aligned.m16n8k8.row.col.f32.tf32.tf32.f32 "
        "{%0,%1,%2,%3}, {%4,%5,%6,%7}, {%8,%9}, {%0,%1,%2,%3};\n"
        : "+f"(d[0]), "+f"(d[1]), "+f"(d[2]), "+f"(d[3])
        : "r"(a[0]), "r"(a[1]), "r"(a[2]), "r"(a[3]), "r"(b[0]), "r"(b[1]));
}

// ---------------- TF32 tensor-core GEMM: C[M,N] = A[M,K] * B[N,K]^T ----------
// Block 128x128, BK=16, 8 warps (2 m-warps x 4 n-warps), warp tile 64x32.
// Smem [row][k], stride 20 (== 4 mod 32 -> conflict-free frag loads).
// EPI: 0=none, 1=RoPE, 2=residual add (aux), 3=SiLU, 4=multiply by aux (gate)
#define KS 20
template<int EPI>
__global__ __launch_bounds__(256) void gemm_tc(
    const float* __restrict__ A, const float* __restrict__ B,
    float* __restrict__ C, const float* __restrict__ aux,
    const float* __restrict__ cosT, const float* __restrict__ sinT,
    int M, int N, int K)
{
    __shared__ float As[2][128][KS];
    __shared__ float Bs[2][128][KS];

    const int tid  = threadIdx.x;
    const int wid  = tid >> 5;
    const int lane = tid & 31;
    const int lr   = lane >> 2;
    const int lc   = lane & 3;
    const int wm   = wid & 1;
    const int wn   = wid >> 1;
    const int m0   = blockIdx.y * 128;
    const int n0   = blockIdx.x * 128;

    const int ar = tid >> 2;
    const int ac = (tid & 3) << 2;

    const float* Aptr = A + (size_t)(m0 + ar) * K + ac;
    const float* Bptr = B + (size_t)(n0 + ar) * K + ac;

    float acc[4][4][4];
    #pragma unroll
    for (int i = 0; i < 4; ++i)
        #pragma unroll
        for (int j = 0; j < 4; ++j)
            #pragma unroll
            for (int c = 0; c < 4; ++c) acc[i][j][c] = 0.0f;

    {
        float4 a0 = cvt4(*(const float4*)(Aptr));
        float4 a1 = cvt4(*(const float4*)(Aptr + (size_t)64 * K));
        float4 b0 = cvt4(*(const float4*)(Bptr));
        float4 b1 = cvt4(*(const float4*)(Bptr + (size_t)64 * K));
        *(float4*)&As[0][ar][ac]      = a0;
        *(float4*)&As[0][ar + 64][ac] = a1;
        *(float4*)&Bs[0][ar][ac]      = b0;
        *(float4*)&Bs[0][ar + 64][ac] = b1;
    }
    __syncthreads();

    int buf = 0;
    for (int k0 = 16; k0 <= K; k0 += 16) {
        float4 a0, a1, b0, b1;
        if (k0 < K) {
            a0 = *(const float4*)(Aptr + k0);
            a1 = *(const float4*)(Aptr + (size_t)64 * K + k0);
            b0 = *(const float4*)(Bptr + k0);
            b1 = *(const float4*)(Bptr + (size_t)64 * K + k0);
        }

        #pragma unroll
        for (int ks8 = 0; ks8 < 2; ++ks8) {
            const int kb = ks8 * 8;
            uint32_t af[4][4], bf[4][2];
            #pragma unroll
            for (int mi = 0; mi < 4; ++mi) {
                const int am = wm * 64 + mi * 16;
                af[mi][0] = __float_as_uint(As[buf][am + lr][kb + lc]);
                af[mi][1] = __float_as_uint(As[buf][am + lr + 8][kb + lc]);
                af[mi][2] = __float_as_uint(As[buf][am + lr][kb + lc + 4]);
                af[mi][3] = __float_as_uint(As[buf][am + lr + 8][kb + lc + 4]);
            }
            #pragma unroll
            for (int nj = 0; nj < 4; ++nj) {
                const int bn = wn * 32 + nj * 8;
                bf[nj][0] = __float_as_uint(Bs[buf][bn + lr][kb + lc]);
                bf[nj][1] = __float_as_uint(Bs[buf][bn + lr][kb + lc + 4]);
            }
            #pragma unroll
            for (int mi = 0; mi < 4; ++mi)
                #pragma unroll
                for (int nj = 0; nj < 4; ++nj)
                    mma_tf32(acc[mi][nj], af[mi], bf[nj]);
        }

        if (k0 < K) {
            const int nb = buf ^ 1;
            *(float4*)&As[nb][ar][ac]      = cvt4(a0);
            *(float4*)&As[nb][ar + 64][ac] = cvt4(a1);
            *(float4*)&Bs[nb][ar][ac]      = cvt4(b0);
            *(float4*)&Bs[nb][ar + 64][ac] = cvt4(b1);
            __syncthreads();
            buf = nb;
        }
    }

    #pragma unroll
    for (int mi = 0; mi < 4; ++mi) {
        const int gm0 = m0 + wm * 64 + mi * 16 + lr;
        const int gm1 = gm0 + 8;
        #pragma unroll
        for (int nj = 0; nj < 4; ++nj) {
            const int gn = n0 + wn * 32 + nj * 8 + 2 * lc;
            float c0 = acc[mi][nj][0], c1 = acc[mi][nj][1];
            float c2 = acc[mi][nj][2], c3 = acc[mi][nj][3];

            if (EPI == 1) {
                const int pi = (gn & 63) >> 1;
                float cs0 = cosT[gm0 * 32 + pi], sn0 = sinT[gm0 * 32 + pi];
                float cs1 = cosT[gm1 * 32 + pi], sn1 = sinT[gm1 * 32 + pi];
                float r0 = c0, i0 = c1, r1 = c2, i1 = c3;
                c0 = r0 * cs0 - i0 * sn0;  c1 = r0 * sn0 + i0 * cs0;
                c2 = r1 * cs1 - i1 * sn1;  c3 = r1 * sn1 + i1 * cs1;
            } else if (EPI == 2) {
                const float2 x0 = *(const float2*)(aux + (size_t)gm0 * N + gn);
                const float2 x1 = *(const float2*)(aux + (size_t)gm1 * N + gn);
                c0 += x0.x; c1 += x0.y; c2 += x1.x; c3 += x1.y;
            } else if (EPI == 3) {
                c0 = c0 / (1.0f + __expf(-c0));
                c1 = c1 / (1.0f + __expf(-c1));
                c2 = c2 / (1.0f + __expf(-c2));
                c3 = c3 / (1.0f + __expf(-c3));
            } else if (EPI == 4) {
                const float2 x0 = *(const float2*)(aux + (size_t)gm0 * N + gn);
                const float2 x1 = *(const float2*)(aux + (size_t)gm1 * N + gn);
                c0 *= x0.x; c1 *= x0.y; c2 *= x1.x; c3 *= x1.y;
            }

            *(float2*)(C + (size_t)gm0 * N + gn) = make_float2(c0, c1);
            *(float2*)(C + (size_t)gm1 * N + gn) = make_float2(c2, c3);
        }
    }
}

// ---------------- TF32 tensor-core flash attention ---------------------------
// Br=128 queries/CTA, Bc=32 keys/tile, 8 warps, each warp owns a 16-row m-tile.
// Q fragments in registers (pre-scaled by 1/8); K in smem [key][dim] (stride 68);
// V transposed [dim][key] (stride 36); P via smem round-trip (warp-local).
__global__ __launch_bounds__(256) void attn_tc(
    const float* __restrict__ Q, const float* __restrict__ Kg,
    const float* __restrict__ Vg, float* __restrict__ O)
{
    __shared__ float Ks[32][68];
    __shared__ float Vt[64][36];
    __shared__ float Ps[128][36];

    const int tid  = threadIdx.x;
    const int wid  = tid >> 5;
    const int lane = tid & 31;
    const int lr   = lane >> 2;
    const int lc   = lane & 3;
    const int wm0  = wid * 16;           // this warp's query-row base
    const int h    = blockIdx.y;
    const int q0   = blockIdx.x * 128;
    const int hoff = h * HD;

    // Q fragments for all 8 k8-steps, pre-scaled by 1/sqrt(64)=0.125 (exact pow2)
    uint32_t qf[8][4];
    {
        const float* Qb = Q + (size_t)(q0 + wm0) * DIM + hoff;
        #pragma unroll
        for (int kb8 = 0; kb8 < 8; ++kb8) {
            const int k = kb8 * 8;
            qf[kb8][0] = __float_as_uint(to_tf32(0.125f * Qb[(size_t)lr * DIM + k + lc]));
            qf[kb8][1] = __float_as_uint(to_tf32(0.125f * Qb[(size_t)(lr + 8) * DIM + k + lc]));
            qf[kb8][2] = __float_as_uint(to_tf32(0.125f * Qb[(size_t)lr * DIM + k + lc + 4]));
            qf[kb8][3] = __float_as_uint(to_tf32(0.125f * Qb[(size_t)(lr + 8) * DIM + k + lc + 4]));
        }
    }

    float m_[2] = {-CUDART_INF_F, -CUDART_INF_F};
    float l_[2] = {0.0f, 0.0f};
    float oacc[8][4];
    #pragma unroll
    for (int nj = 0; nj < 8; ++nj)
        #pragma unroll
        for (int c = 0; c < 4; ++c) oacc[nj][c] = 0.0f;

    for (int t0 = 0; t0 < SEQ; t0 += 32) {
        __syncthreads();   // prior tile's Ks/Vt consumers done
        {
            // stage K tile [32 keys][64 dims] and V transposed [64 dims][32 keys]
            const int c  = tid >> 3;          // 0..31 key
            const int ds = (tid & 7) << 3;    // 0,8,...,56 dim
            const float* kp = Kg + (size_t)(t0 + c) * DIM + hoff + ds;
            float4 k0v = cvt4(*(const float4*)(kp));
            float4 k1v = cvt4(*(const float4*)(kp + 4));
            *(float4*)&Ks[c][ds]     = k0v;
            *(float4*)&Ks[c][ds + 4] = k1v;
            const float* vp = Vg + (size_t)(t0 + c) * DIM + hoff + ds;
            float4 v0 = cvt4(*(const float4*)(vp));
            float4 v1 = cvt4(*(const float4*)(vp + 4));
            Vt[ds + 0][c] = v0.x; Vt[ds + 1][c] = v0.y; Vt[ds + 2][c] = v0.z; Vt[ds + 3][c] = v0.w;
            Vt[ds + 4][c] = v1.x; Vt[ds + 5][c] = v1.y; Vt[ds + 6][c] = v1.z; Vt[ds + 7][c] = v1.w;
        }
        __syncthreads();

        // S = Q*K^T (scaled): warp tile 16 x 32, 4 n-steps x 8 k-steps
        float sfr[4][4];
        #pragma unroll
        for (int nj = 0; nj < 4; ++nj)
            #pragma unroll
            for (int c = 0; c < 4; ++c) sfr[nj][c] = 0.0f;

        #pragma unroll
        for (int kb8 = 0; kb8 < 8; ++kb8) {
            const int kb = kb8 * 8;
            uint32_t bf[4][2];
            #pragma unroll
            for (int nj = 0; nj < 4; ++nj) {
                const int bn = nj * 8;
                bf[nj][0] = __float_as_uint(Ks[bn + lr][kb + lc]);
                bf[nj][1] = __float_as_uint(Ks[bn + lr][kb + lc + 4]);
            }
            #pragma unroll
            for (int nj = 0; nj < 4; ++nj)
                mma_tf32(sfr[nj], qf[kb8], bf[nj]);
        }

        // online softmax: rows lr (c0,c1) and lr+8 (c2,c3)
        float mt0 = -CUDART_INF_F, mt1 = -CUDART_INF_F;
        #pragma unroll
        for (int nj = 0; nj < 4; ++nj) {
            mt0 = fmaxf(mt0, fmaxf(sfr[nj][0], sfr[nj][1]));
            mt1 = fmaxf(mt1, fmaxf(sfr[nj][2], sfr[nj][3]));
        }
        mt0 = fmaxf(mt0, __shfl_xor_sync(0xffffffffu, mt0, 1));
        mt0 = fmaxf(mt0, __shfl_xor_sync(0xffffffffu, mt0, 2));
        mt1 = fmaxf(mt1, __shfl_xor_sync(0xffffffffu, mt1, 1));
        mt1 = fmaxf(mt1, __shfl_xor_sync(0xffffffffu, mt1, 2));

        const float mn0 = fmaxf(m_[0], mt0);
        const float mn1 = fmaxf(m_[1], mt1);
        const float al0 = __expf(m_[0] - mn0);
        const float al1 = __expf(m_[1] - mn1);
        m_[0] = mn0; m_[1] = mn1;

        float rs0 = 0.0f, rs1 = 0.0f;
        #pragma unroll
        for (int nj = 0; nj < 4; ++nj) {
            sfr[nj][0] = __expf(sfr[nj][0] - mn0);
            sfr[nj][1] = __expf(sfr[nj][1] - mn0);
            sfr[nj][2] = __expf(sfr[nj][2] - mn1);
            sfr[nj][3] = __expf(sfr[nj][3] - mn1);
            rs0 += sfr[nj][0] + sfr[nj][1];
            rs1 += sfr[nj][2] + sfr[nj][3];
        }
        rs0 += __shfl_xor_sync(0xffffffffu, rs0, 1);
        rs0 += __shfl_xor_sync(0xffffffffu, rs0, 2);
        rs1 += __shfl_xor_sync(0xffffffffu, rs1, 1);
        rs1 += __shfl_xor_sync(0xffffffffu, rs1, 2);
        l_[0] = l_[0] * al0 + rs0;
        l_[1] = l_[1] * al1 + rs1;

        // write P (tf32) to Ps for C->A fragment re-layout (warp-local rows)
        #pragma unroll
        for (int nj = 0; nj < 4; ++nj) {
            const int cn = nj * 8 + 2 * lc;
            *(float2*)&Ps[wm0 + lr][cn]     = make_float2(to_tf32(sfr[nj][0]), to_tf32(sfr[nj][1]));
            *(float2*)&Ps[wm0 + 8 + lr][cn] = make_float2(to_tf32(sfr[nj][2]), to_tf32(sfr[nj][3]));
        }
        // rescale O accumulators
        #pragma unroll
        for (int nj = 0; nj < 8; ++nj) {
            oacc[nj][0] *= al0; oacc[nj][1] *= al0;
            oacc[nj][2] *= al1; oacc[nj][3] *= al1;
        }
        __syncwarp();

        // O += P @ V : 8 n-steps (dims) x 4 k-steps (keys)
        #pragma unroll
        for (int kb8 = 0; kb8 < 4; ++kb8) {
            const int kb = kb8 * 8;
            uint32_t af[4];
            af[0] = __float_as_uint(Ps[wm0 + lr][kb + lc]);
            af[1] = __float_as_uint(Ps[wm0 + 8 + lr][kb + lc]);
            af[2] = __float_as_uint(Ps[wm0 + lr][kb + lc + 4]);
            af[3] = __float_as_uint(Ps[wm0 + 8 + lr][kb + lc + 4]);
            #pragma unroll
            for (int nj = 0; nj < 8; ++nj) {
                const int bn = nj * 8;
                uint32_t bf2[2];
                bf2[0] = __float_as_uint(Vt[bn + lr][kb + lc]);
                bf2[1] = __float_as_uint(Vt[bn + lr][kb + lc + 4]);
                mma_tf32(oacc[nj], af, bf2);
            }
        }
    }

    // finalize
    const float inv0 = 1.0f / l_[0];
    const float inv1 = 1.0f / l_[1];
    #pragma unroll
    for (int nj = 0; nj < 8; ++nj) {
        const int gd = hoff + nj * 8 + 2 * lc;
        *(float2*)(O + (size_t)(q0 + wm0 + lr) * DIM + gd) =
            make_float2(oacc[nj][0] * inv0, oacc[nj][1] * inv0);
        *(float2*)(O + (size_t)(q0 + wm0 + 8 + lr) * DIM + gd) =
            make_float2(oacc[nj][2] * inv1, oacc[nj][3] * inv1);
    }
}

// ---------------- launch ------------------------------------------------------
extern "C" void kernel_launch(void* const* d_in, const int* in_sizes, int n_in,
                              void* d_out, int out_size)
{
    (void)in_sizes; (void)n_in; (void)out_size;
    const float* x  = (const float*)d_in[0];
    const float* wq = (const float*)d_in[1];
    const float* wk = (const float*)d_in[2];
    const float* wv = (const float*)d_in[3];
    const float* wo = (const float*)d_in[4];
    const float* w1 = (const float*)d_in[5];
    const float* w2 = (const float*)d_in[6];
    const float* w3 = (const float*)d_in[7];
    const float* ga = (const float*)d_in[8];
    const float* gf = (const float*)d_in[9];
    float* out = (float*)d_out;

    float *xn, *qb, *kb, *vb, *ao, *hb, *hn, *ff, *ct, *st;
    cudaGetSymbolAddress((void**)&xn, g_xn);
    cudaGetSymbolAddress((void**)&qb, g_qb);
    cudaGetSymbolAddress((void**)&kb, g_kb);
    cudaGetSymbolAddress((void**)&vb, g_vb);
    cudaGetSymbolAddress((void**)&ao, g_ao);
    cudaGetSymbolAddress((void**)&hb, g_hb);
    cudaGetSymbolAddress((void**)&hn, g_hn);
    cudaGetSymbolAddress((void**)&ff, g_ff);
    cudaGetSymbolAddress((void**)&ct, g_cos);
    cudaGetSymbolAddress((void**)&st, g_sin);

    rope_tab_k<<<(SEQ * 32) / 256, 256>>>(ct, st);
    rmsnorm_k<<<SEQ, 256>>>(x, ga, xn);

    dim3 blk(256);
    dim3 gD(DIM / 128, SEQ / 128);
    dim3 gH(HID / 128, SEQ / 128);

    gemm_tc<1><<<gD, blk>>>(xn, wq, qb, nullptr, ct, st, SEQ, DIM, DIM);
    gemm_tc<1><<<gD, blk>>>(xn, wk, kb, nullptr, ct, st, SEQ, DIM, DIM);
    gemm_tc<0><<<gD, blk>>>(xn, wv, vb, nullptr, nullptr, nullptr, SEQ, DIM, DIM);

    attn_tc<<<dim3(SEQ / 128, NH), 256>>>(qb, kb, vb, ao);

    gemm_tc<2><<<gD, blk>>>(ao, wo, hb, x, nullptr, nullptr, SEQ, DIM, DIM);
    rmsnorm_k<<<SEQ, 256>>>(hb, gf, hn);
    gemm_tc<3><<<gH, blk>>>(hn, w1, ff, nullptr, nullptr, nullptr, SEQ, HID, DIM);
    gemm_tc<4><<<gH, blk>>>(hn, w3, ff, ff, nullptr, nullptr, SEQ, HID, DIM);
    gemm_tc<2><<<gD, blk>>>(ff, w2, out, hb, nullptr, nullptr, SEQ, DIM, HID);
}